// round 3
// baseline (speedup 1.0000x reference)
#include <cuda_runtime.h>
#include <cstdint>

// FP32->FP8(E4M3) bit-pulse converter.
// Input:  [N, 32] floats (0.0/1.0) = [S, E7..E0, M22..M0]  (IEEE-754 order, MSB first)
// Output: [N, 8]  floats (0.0/1.0) = [S, E3..E0, M2..M0]
//
// Strategy: one warp per 32 values. For value v, lane l loads pulse l
// (perfectly coalesced 128B line); __ballot_sync + __brev rebuilds the
// IEEE fp32 bit word in every lane. Each lane keeps the 8 words it needs
// so the 8 output stores per lane are also perfectly coalesced.

__global__ __launch_bounds__(256, 8)
void fp32_to_fp8_pulse_kernel(const uint32_t* __restrict__ in,
                              float* __restrict__ out,
                              int n_vals)
{
    const int lane  = threadIdx.x & 31;
    const int warpG = (int)((blockIdx.x * blockDim.x + threadIdx.x) >> 5);
    const int vbase = warpG * 32;              // first value this warp handles
    if (vbase >= n_vals) return;

    const uint32_t* inw = in + (size_t)vbase * 32;

    // ---- gather 32 fp32 bit-words via ballot ----
    // Iteration v: lane l loads pulse l of value (vbase+v). Ballot bit l =
    // pulse l; __brev puts pulse 0 (sign) at bit 31 -> exact IEEE layout.
    // Lane l only needs values {4j + (l>>3)} for its coalesced output slots,
    // i.e. keep word when (v & 3) == (l >> 3), stored at index v >> 2.
    uint32_t words[8];
    const int keep_r = lane >> 3;
#pragma unroll
    for (int v = 0; v < 32; ++v) {
        uint32_t x = __ldcs(inw + v * 32 + lane);       // 0x00000000 or 0x3F800000
        unsigned m = __ballot_sync(0xFFFFFFFFu, x != 0u);
        if ((v & 3) == keep_r) words[v >> 2] = __brev(m);
    }

    float* o = out + (size_t)vbase * 8;
    const int obit = 7 - (lane & 7);   // output position (l&7): 0=S(bit7) ... 7=M0(bit0)

#pragma unroll
    for (int j = 0; j < 8; ++j) {
        uint32_t w    = words[j];
        uint32_t s    = w >> 31;
        uint32_t exp  = (w >> 23) & 0xFFu;
        uint32_t mant = w & 0x7FFFFFu;

        // ---- normal path: exp8 = exp - 120, RNE 23 -> 3 mantissa bits ----
        uint32_t kept  = mant >> 20;
        uint32_t R     = (mant >> 19) & 1u;
        uint32_t S     = (mant & 0x7FFFFu) != 0u;
        uint32_t ru    = R & (S | (kept & 1u));
        uint32_t mr    = kept + ru;                     // may carry into bit 3
        uint32_t carry = mr >> 3;
        uint32_t mant_norm = carry ? 0u : (mr & 7u);
        uint32_t exp_norm  = exp - 120u + carry;

        // ---- subnormal path (117 <= exp <= 120): shift 1.mant right, RNE ----
        uint32_t full = 0x800000u | mant;               // 24-bit 1.mant
        int sh = 141 - (int)exp;
        sh = sh < 1 ? 1 : (sh > 24 ? 24 : sh);
        uint32_t kept_s = full >> sh;
        uint32_t Rs = (full >> (sh - 1)) & 1u;
        uint32_t Ss = (full & ((1u << (sh - 1)) - 1u)) != 0u;
        uint32_t ms = kept_s + (Rs & (Ss | (kept_s & 1u)));
        uint32_t sub_of   = ms >= 8u;
        uint32_t sub_exp  = sub_of ? 1u : 0u;
        uint32_t sub_mant = sub_of ? 0u : ms;

        // ---- select overflow / subnormal / underflow / normal ----
        uint32_t exp8, mant8;
        if (exp > 134u)                      { exp8 = 15u;      mant8 = 6u; }
        else if (exp >= 117u && exp <= 120u) { exp8 = sub_exp;  mant8 = sub_mant; }
        else if (exp < 117u)                 { exp8 = 0u;       mant8 = 0u; }
        else                                 { exp8 = exp_norm; mant8 = mant_norm; }

        uint32_t res = (s << 7) | (exp8 << 3) | mant8;  // [S,E3..E0,M2..M0] MSB..LSB
        __stcs(o + j * 32 + lane, (float)((res >> obit) & 1u));
    }
}

extern "C" void kernel_launch(void* const* d_in, const int* in_sizes, int n_in,
                              void* d_out, int out_size)
{
    const uint32_t* in = (const uint32_t*)d_in[0];
    float* out = (float*)d_out;
    int n_vals = in_sizes[0] / 32;           // 2,097,152
    // one warp per 32 values; 256 threads = 8 warps per block
    int warps  = (n_vals + 31) / 32;
    int blocks = (warps + 7) / 8;
    fp32_to_fp8_pulse_kernel<<<blocks, 256>>>(in, out, n_vals);
}

// round 5
// speedup vs baseline: 1.0893x; 1.0893x over previous
#include <cuda_runtime.h>
#include <cstdint>

// FP32->FP8(E4M3) bit-pulse converter.
// Input:  [N, 32] floats (0.0/1.0) = [S, E7..E0, M22..M0]  (IEEE order, MSB first)
// Output: [N, 8]  floats (0.0/1.0) = [S, E3..E0, M2..M0]
//
// One warp per 32 values.
//  Load:    32 coalesced LDG.32 + 32 ballots; lane v keeps value v's bit word.
//  Convert: each lane converts exactly ONE value (no redundancy).
//  Store:   8 ballots transpose the 8-bit results back into the coalesced
//           output layout; 8 coalesced STG.32 per lane.

__global__ __launch_bounds__(256)
void fp32_to_fp8_pulse_kernel(const uint32_t* __restrict__ in,
                              float* __restrict__ out,
                              int n_vals)
{
    const int lane  = threadIdx.x & 31;
    const int warpG = (int)((blockIdx.x * blockDim.x + threadIdx.x) >> 5);
    const int vbase = warpG * 32;                 // first value this warp handles
    if (vbase >= n_vals) return;

    const uint32_t* inw = in + (size_t)vbase * 32;

    // ---- gather: iteration v, lane l loads pulse l of value (vbase+v).
    // ballot bit l = pulse l; brev puts pulse 0 (sign) at bit 31 -> IEEE word.
    // Lane l keeps the word of value l.
    uint32_t myword = 0;
#pragma unroll
    for (int v = 0; v < 32; ++v) {
        uint32_t x = __ldcs(inw + v * 32 + lane);        // 0x0 or 0x3F800000
        unsigned m = __ballot_sync(0xFFFFFFFFu, x != 0u);
        if (v == lane) myword = m;
    }
    const uint32_t w = __brev(myword);

    // ---- convert this lane's single value ----
    uint32_t s    = w >> 31;
    uint32_t exp  = (w >> 23) & 0xFFu;
    uint32_t mant = w & 0x7FFFFFu;

    // normal path: exp8 = exp - 120, RNE 23 -> 3 mantissa bits
    uint32_t kept  = mant >> 20;
    uint32_t R     = (mant >> 19) & 1u;
    uint32_t S     = (mant & 0x7FFFFu) != 0u;
    uint32_t mr    = kept + (R & (S | (kept & 1u)));     // may carry into bit 3
    uint32_t carry = mr >> 3;
    uint32_t mant_norm = carry ? 0u : (mr & 7u);
    uint32_t exp_norm  = exp - 120u + carry;

    // subnormal path (117 <= exp <= 120): shift 1.mant right, RNE
    uint32_t full = 0x800000u | mant;                    // 24-bit 1.mant
    int sh = 141 - (int)exp;
    sh = sh < 1 ? 1 : (sh > 24 ? 24 : sh);
    uint32_t kept_s = full >> sh;
    uint32_t Rs = (full >> (sh - 1)) & 1u;
    uint32_t Ss = (full & ((1u << (sh - 1)) - 1u)) != 0u;
    uint32_t ms = kept_s + (Rs & (Ss | (kept_s & 1u)));
    uint32_t sub_of   = ms >= 8u;
    uint32_t sub_exp  = sub_of ? 1u : 0u;
    uint32_t sub_mant = sub_of ? 0u : ms;

    // select overflow / subnormal / underflow / normal
    uint32_t exp8, mant8;
    if (exp > 134u)                      { exp8 = 15u;      mant8 = 6u; }
    else if (exp >= 117u && exp <= 120u) { exp8 = sub_exp;  mant8 = sub_mant; }
    else if (exp < 117u)                 { exp8 = 0u;       mant8 = 0u; }
    else                                 { exp8 = exp_norm; mant8 = mant_norm; }

    const uint32_t res = (s << 7) | (exp8 << 3) | mant8; // bit7=S ... bit0=M0

    // ---- output transpose via ballots ----
    // mask_b bit v = output bit b of value v (lane v holds value v's res).
    // Output slot j*32+lane = value (4j + lane>>3), bit (lane&7).
    const int myb = lane & 7;
    uint32_t mymask = 0;
#pragma unroll
    for (int b = 0; b < 8; ++b) {
        unsigned mb = __ballot_sync(0xFFFFFFFFu, (res >> (7 - b)) & 1u);
        if (b == myb) mymask = mb;
    }

    float* o = out + (size_t)vbase * 8;
    const int r = lane >> 3;
#pragma unroll
    for (int j = 0; j < 8; ++j) {
        uint32_t bit = (mymask >> (4 * j + r)) & 1u;
        __stcs(o + j * 32 + lane, __uint_as_float(0x3F800000u & (0u - bit)));
    }
}

extern "C" void kernel_launch(void* const* d_in, const int* in_sizes, int n_in,
                              void* d_out, int out_size)
{
    const uint32_t* in = (const uint32_t*)d_in[0];
    float* out = (float*)d_out;
    int n_vals = in_sizes[0] / 32;               // 2,097,152
    int warps  = (n_vals + 31) / 32;
    int blocks = (warps + 7) / 8;                // 256 threads = 8 warps/block
    fp32_to_fp8_pulse_kernel<<<blocks, 256>>>(in, out, n_vals);
}